// round 9
// baseline (speedup 1.0000x reference)
#include <cuda_runtime.h>
#include <math.h>

#define N_ANCH 10647
#define OFF1   8112     // 52*52*3
#define OFF2   10140    // OFF1 + 26*26*3
#define HW0    2704     // 52*52
#define HW1    676      // 26*26
#define HW2    169      // 13*13
#define CONF_T 0.001f
#define NCLS   20
#define CCAP   1024     // per-class capacity (mean ~532, sd ~22.5)
#define MAXW   (CCAP/32)
#define STRIPS 8

// ---------------- device scratch (static, no allocation) ----------------
__device__ float4             d_boxes[N_ANCH];          // decoded boxes (unclipped, normalized)
__device__ unsigned long long d_ckey [NCLS * CCAP];     // per-class keys (~score<<32 | idx)
__device__ int                d_ccnt [NCLS];            // per-class counts (self-resetting)
__device__ int                d_snc  [NCLS];            // clamped counts for build/sweep
__device__ unsigned long long d_skey [NCLS * CCAP];     // sorted keys
__device__ float4             d_sbox [NCLS * CCAP];     // sorted boxes
__device__ float              d_sarea[NCLS * CCAP];     // sorted areas
__device__ unsigned int       d_validw[NCLS * 32];      // validity bits, packed
__device__ unsigned int       d_colany[NCLS * 32];      // column has some earlier conflict
__device__ unsigned int       d_rowany[NCLS * 32];      // row has some later conflict
__device__ unsigned int       d_masks[NCLS * CCAP * MAXW]; // conflict bit-matrix rows

// anchors[scale][a][wh], already multiplied by {4,2,1}
__constant__ float c_anch[3][3][2] = {
    {{ 4.f, 6.f},{ 8.f,12.f},{12.f,10.f}},   // stride 8
    {{ 3.f, 7.f},{ 6.f, 8.f},{ 8.f, 6.f}},   // stride 16
    {{3.5f, 5.f},{ 5.f,4.5f},{ 8.f, 8.f}}    // stride 32
};

__device__ __forceinline__ float sigmoidf_(float v) { return 1.f / (1.f + expf(-v)); }

// ---------------- kernel 1: decode batch 0 + class bucketing (coalesced) ----------------
__global__ void k_decode(const float* __restrict__ p0,
                         const float* __restrict__ p1,
                         const float* __restrict__ p2,
                         float* __restrict__ out)
{
    int t = blockIdx.x * blockDim.x + threadIdx.x;
    if (t >= N_ANCH) return;

    const float* p; int G, HW, off, sc; float st;
    if (t < OFF1)      { p = p0; G = 52; HW = HW0; off = 0;    sc = 0; st =  8.f; }
    else if (t < OFF2) { p = p1; G = 26; HW = HW1; off = OFF1; sc = 1; st = 16.f; }
    else               { p = p2; G = 13; HW = HW2; off = OFF2; sc = 2; st = 32.f; }

    int rel = t - off;
    int a   = rel / HW;
    int hw  = rel - a * HW;
    int y   = hw / G;
    int x   = hw - y * G;
    int GG  = HW;
    int idx = off + hw * 3 + a;                // original anchor index
    const float* base = p + hw;                // batch 0, channel stride = GG

    float obj = sigmoidf_(base[(size_t)a * GG]);

    float l[NCLS];
    float m = -3.4e38f; int am = 0;
#pragma unroll
    for (int c = 0; c < NCLS; c++) {
        l[c] = base[(size_t)(3 + a * NCLS + c) * GG];
        if (l[c] > m) { m = l[c]; am = c; }
    }
    float s = 0.f;
#pragma unroll
    for (int c = 0; c < NCLS; c++) s += expf(l[c] - m);
    float score = obj * (1.f / s);

    float tx = base[(size_t)(63 + a * 4 + 0) * GG];
    float ty = base[(size_t)(63 + a * 4 + 1) * GG];
    float tw = base[(size_t)(63 + a * 4 + 2) * GG];
    float th = base[(size_t)(63 + a * 4 + 3) * GG];

    float cx = sigmoidf_(tx) + (float)x;
    float cy = sigmoidf_(ty) + (float)y;

    float aw, ah;
    if (hw == GG - 1) { aw = 0.f; ah = 0.f; }
    else { aw = c_anch[sc][a][0]; ah = c_anch[sc][a][1]; }

    float bw = expf(tw) * aw;
    float bh = expf(th) * ah;

    float x1 = (cx - bw * 0.5f) * st / 416.f;
    float y1 = (cy - bh * 0.5f) * st / 416.f;
    float x2 = (cx + bw * 0.5f) * st / 416.f;
    float y2 = (cy + bh * 0.5f) * st / 416.f;

    d_boxes[idx] = make_float4(x1, y1, x2, y2);

    unsigned long long key =
        ((unsigned long long)(~__float_as_uint(score)) << 32) | (unsigned)idx;
    int pos = atomicAdd(&d_ccnt[am], 1);
    if (pos < CCAP) d_ckey[am * CCAP + pos] = key;

    float4 ob;
    ob.x = fminf(fmaxf(x1 * 416.f, 0.f), 415.f) / 416.f;
    ob.y = fminf(fmaxf(y1 * 416.f, 0.f), 415.f) / 416.f;
    ob.z = fminf(fmaxf(x2 * 416.f, 0.f), 415.f) / 416.f;
    ob.w = fminf(fmaxf(y2 * 416.f, 0.f), 415.f) / 416.f;
    *(float4*)(out + (size_t)idx * 4) = ob;
    out[4 * N_ANCH + idx] = score;
    out[5 * N_ANCH + idx] = (float)am;
}

// ---------------- kernel 2: hybrid register/shfl bitonic sort + gather ----------------
__global__ void __launch_bounds__(1024) k_sortgather()
{
    __shared__ unsigned long long sx[CCAP];    // exchange buffer for j>=32 steps
    const int c    = blockIdx.x;
    const int tid  = threadIdx.x;
    const int lane = tid & 31;
    const int wrp  = tid >> 5;

    int nc = d_ccnt[c];
    if (nc > CCAP) nc = CCAP;

    unsigned long long v = (tid < nc) ? d_ckey[c * CCAP + tid] : 0xFFFFFFFFFFFFFFFFULL;

    // bitonic: real keys are distinct (idx in low bits) -> min/max comparator safe
    for (int k = 2; k <= CCAP; k <<= 1) {
        int j = k >> 1;
        for (; j >= 32; j >>= 1) {             // cross-warp: smem exchange
            sx[tid] = v;
            __syncthreads();
            unsigned long long o = sx[tid ^ j];
            bool takeMin = (((tid & j) == 0) == ((tid & k) == 0));
            v = takeMin ? (v < o ? v : o) : (v < o ? o : v);
            __syncthreads();
        }
        for (; j > 0; j >>= 1) {               // intra-warp: shfl, no barriers
            unsigned long long o = __shfl_xor_sync(0xFFFFFFFFu, v, j);
            bool takeMin = (((lane & j) == 0) == ((tid & k) == 0));
            v = takeMin ? (v < o ? v : o) : (v < o ? o : v);
        }
    }

    // thread tid now holds rank-tid element
    d_skey[c * CCAP + tid] = v;
    bool valid = false;
    if (tid < nc) {
        int o = (int)(v & 0xFFFFFFFFULL);
        float4 b = d_boxes[o];
        d_sbox [c * CCAP + tid] = b;
        d_sarea[c * CCAP + tid] = (b.z - b.x) * (b.w - b.y);
        valid = (__uint_as_float(~(unsigned)(v >> 32)) >= CONF_T);
    }
    unsigned vb = __ballot_sync(0xFFFFFFFFu, valid);
    if (lane == 0) d_validw[c * 32 + wrp] = vb;
    if (tid < 32) { d_colany[c * 32 + tid] = 0u; d_rowany[c * 32 + tid] = 0u; }
    if (tid == 0) { d_snc[c] = nc; d_ccnt[c] = 0; }   // self-reset for next replay
}

// ---------------- kernel 3: conflict-mask build, 8 strips x 20 classes ----------------
__global__ void __launch_bounds__(256) k_build()
{
    __shared__ float4 sb[CCAP];
    __shared__ float  sa[CCAP];
    const int c   = blockIdx.y;
    const int s   = blockIdx.x;
    const int tid = threadIdx.x;

    const int nc = d_snc[c];
    const int nwords = (nc + 31) >> 5;
    if (s >= nwords) return;

    for (int i = tid; i < nc; i += 256) {
        sb[i] = d_sbox [c * CCAP + i];
        sa[i] = d_sarea[c * CCAP + i];
    }
    __syncthreads();

    // interleaved words for balance: w = s, s+8, s+16, ...
    for (int w = s; w < nwords; w += STRIPS) {
        int j0   = w << 5;
        int rows = min(nc, j0 + 32);           // rows >= j0+32 have structurally-zero masks
        for (int i = tid; i < rows; i += 256) { // lanes: consecutive i, shared w -> broadcast loads
            float4 bi = sb[i];
            float  ai = sa[i];
            unsigned bits = 0u;
#pragma unroll
            for (int u = 0; u < 32; u++) {
                int j = j0 + u;
                float4 bj = sb[j];             // broadcast across lanes
                float xx1 = fmaxf(bi.x, bj.x);
                float yy1 = fmaxf(bi.y, bj.y);
                float xx2 = fminf(bi.z, bj.z);
                float yy2 = fminf(bi.w, bj.w);
                float inter = fmaxf(1e-28f, xx2 - xx1) * fmaxf(1e-28f, yy2 - yy1);
                float denom = ai + sa[j] - inter;
                // iou > 0.5 exactly: denom>0 -> inter>denom/2; denom==0 -> inter>0; denom<0 -> never
                bool conf = (j > i) && (j < nc) && (denom >= 0.f) && (inter > 0.5f * denom);
                bits |= ((unsigned)conf) << u;
            }
            d_masks[((size_t)c * CCAP + i) * MAXW + w] = bits;
            if (bits) {
                atomicOr(&d_colany[c * 32 + w], bits);
                atomicOr(&d_rowany[c * 32 + (i >> 5)], 1u << (i & 31));
            }
        }
    }
}

// ---------------- kernel 4: word-granular sweep, branchless pipelined fast path ----------------
__global__ void __launch_bounds__(1024) k_sweep(float* __restrict__ out)
{
    extern __shared__ unsigned int dyn[];
    unsigned int* smask = dyn;                 // ninv*32 mask words (worst 128 KB)
    __shared__ int          rows_s[CCAP];      // compacted involved-row indices (ascending)
    __shared__ unsigned int validw_s[32], inv_s[32], keep_s[32], diagnz_s[32];
    __shared__ int          P[33];             // prefix offsets of involved rows per word

    const int c    = blockIdx.x;
    const int tid  = threadIdx.x;
    const int lane = tid & 31;
    const int nc   = d_snc[c];
    const int nwords = (nc + 31) >> 5;

    if (tid < 32) {
        unsigned ca = d_colany[c * 32 + tid];
        unsigned ra = d_rowany[c * 32 + tid];
        validw_s[tid] = d_validw[c * 32 + tid];
        unsigned iv   = ca | ra;               // rows whose masks we stage
        inv_s[tid]    = iv;
        keep_s[tid]   = 0u;
        diagnz_s[tid] = 0u;
        // warp-parallel inclusive scan of popcounts -> prefix table
        int scan = __popc(iv);
#pragma unroll
        for (int d = 1; d < 32; d <<= 1) {
            int nvl = __shfl_up_sync(0xFFFFFFFFu, scan, d);
            if (lane >= d) scan += nvl;
        }
        P[tid + 1] = scan;
        if (tid == 0) P[0] = 0;
    }
    __syncthreads();
    const int ninv = P[32];

    // compacted ascending list: rows_s[slot] = i
    if (tid < nc) {
        unsigned w = inv_s[tid >> 5];
        if ((w >> lane) & 1u)
            rows_s[P[tid >> 5] + __popc(w & ((1u << lane) - 1u))] = tid;
    }
    __syncthreads();

    // copy involved rows' masks to smem; flag words containing intra-word conflicts
    for (int t = tid; t < ninv * 32; t += 1024) {
        int s = t >> 5, ln = t & 31;
        int i = rows_s[s];
        unsigned v = (ln >= (i >> 5) && ln < nwords)
                   ? d_masks[((size_t)c * CCAP + i) * MAXW + ln] : 0u;
        smask[t] = v;
        if (v && ln == (i >> 5))               // nonzero diagonal word -> intra-word conflict
            atomicOr(&diagnz_s[ln], 1u);
    }
    __syncthreads();

    // single-warp word-granular sweep; lane l owns supp word for columns [32l, 32l+32)
    if (tid < 32) {
        unsigned supp = 0u;
        for (int wi = 0; wi < nwords; wi++) {
            unsigned sw   = __shfl_sync(0xFFFFFFFFu, supp, wi);  // suppression from earlier words
            unsigned cand = validw_s[wi] & ~sw;                  // uniform across lanes
            int s0 = P[wi], s1 = P[wi + 1];
            if (diagnz_s[wi] == 0u) {
                // fast path: cand is final; branchless predicated ORs, 4 LDS in flight
                int s = s0;
                for (; s + 4 <= s1; s += 4) {
                    int b0 = rows_s[s]     & 31;
                    int b1 = rows_s[s + 1] & 31;
                    int b2 = rows_s[s + 2] & 31;
                    int b3 = rows_s[s + 3] & 31;
                    unsigned r0 = smask[( s      << 5) + lane] & (0u - ((cand >> b0) & 1u));
                    unsigned r1 = smask[((s + 1) << 5) + lane] & (0u - ((cand >> b1) & 1u));
                    unsigned r2 = smask[((s + 2) << 5) + lane] & (0u - ((cand >> b2) & 1u));
                    unsigned r3 = smask[((s + 3) << 5) + lane] & (0u - ((cand >> b3) & 1u));
                    supp |= (r0 | r1) | (r2 | r3);
                }
                for (; s < s1; s++) {
                    int b = rows_s[s] & 31;
                    supp |= smask[(s << 5) + lane] & (0u - ((cand >> b) & 1u));
                }
            } else {
                // slow path: ascending-bit resolution; cand stays warp-uniform
                for (int s = s0; s < s1; s++) {
                    int b = rows_s[s] & 31;
                    if ((cand >> b) & 1u) {                      // uniform branch
                        unsigned rv = smask[(s << 5) + lane];
                        supp |= rv;
                        cand &= ~__shfl_sync(0xFFFFFFFFu, rv, wi); // its intra-word (bits > b) mask
                    }
                }
            }
            if (lane == 0) keep_s[wi] = cand;  // exact keep word (incl. non-involved rows)
        }
    }
    __syncthreads();

    // scatter keep flags back to original indices
    for (int r = tid; r < nc; r += 1024) {
        int o = (int)(d_skey[c * CCAP + r] & 0xFFFFFFFFULL);
        out[6 * N_ANCH + o] = ((keep_s[r >> 5] >> (r & 31)) & 1u) ? 1.f : 0.f;
    }
}

// ---------------- launch ----------------
extern "C" void kernel_launch(void* const* d_in, const int* in_sizes, int n_in,
                              void* d_out, int out_size)
{
    const float* p0 = (const float*)d_in[0];   // pred_1 (64,75,52,52)
    const float* p1 = (const float*)d_in[1];   // pred_2 (64,75,26,26)
    const float* p2 = (const float*)d_in[2];   // pred_3 (64,75,13,13)
    float* out = (float*)d_out;

    const int sweep_smem = CCAP * MAXW * 4;    // worst-case 128 KB (all rows involved)
    cudaFuncSetAttribute(k_sweep, cudaFuncAttributeMaxDynamicSharedMemorySize, sweep_smem);

    k_decode    <<<(N_ANCH + 127) / 128, 128>>>(p0, p1, p2, out);
    k_sortgather<<<NCLS, 1024>>>();
    k_build     <<<dim3(STRIPS, NCLS), 256>>>();
    k_sweep     <<<NCLS, 1024, sweep_smem>>>(out);
}

// round 10
// speedup vs baseline: 1.1756x; 1.1756x over previous
#include <cuda_runtime.h>
#include <math.h>

#define N_ANCH 10647
#define OFF1   8112     // 52*52*3
#define OFF2   10140    // OFF1 + 26*26*3
#define HW0    2704     // 52*52
#define HW1    676      // 26*26
#define HW2    169      // 13*13
#define CONF_T 0.001f
#define NCLS   20
#define CCAP   1024     // per-class capacity (mean ~532, sd ~22.5)
#define MAXW   (CCAP/32)
#define STRIPS 8
#define SPITCH 33       // smem mask pitch (bank-conflict-free for warp-per-word reads)

// ---------------- device scratch (static, no allocation) ----------------
__device__ float4             d_boxes[N_ANCH];          // decoded boxes (unclipped, normalized)
__device__ unsigned long long d_ckey [NCLS * CCAP];     // per-class keys (~score<<32 | idx)
__device__ int                d_ccnt [NCLS];            // per-class counts (self-resetting)
__device__ int                d_snc  [NCLS];            // clamped counts for build/sweep
__device__ unsigned long long d_skey [NCLS * CCAP];     // sorted keys
__device__ float4             d_sbox [NCLS * CCAP];     // sorted boxes
__device__ float              d_sarea[NCLS * CCAP];     // sorted areas
__device__ unsigned int       d_validw[NCLS * 32];      // validity bits, packed
__device__ unsigned int       d_colany[NCLS * 32];      // column has some earlier conflict
__device__ unsigned int       d_rowany[NCLS * 32];      // row has some later conflict
__device__ unsigned int       d_masks[NCLS * CCAP * MAXW]; // conflict bit-matrix rows

// anchors[scale][a][wh], already multiplied by {4,2,1}
__constant__ float c_anch[3][3][2] = {
    {{ 4.f, 6.f},{ 8.f,12.f},{12.f,10.f}},   // stride 8
    {{ 3.f, 7.f},{ 6.f, 8.f},{ 8.f, 6.f}},   // stride 16
    {{3.5f, 5.f},{ 5.f,4.5f},{ 8.f, 8.f}}    // stride 32
};

__device__ __forceinline__ float sigmoidf_(float v) { return 1.f / (1.f + expf(-v)); }

// ---------------- kernel 1: decode batch 0 + class bucketing (coalesced) ----------------
__global__ void k_decode(const float* __restrict__ p0,
                         const float* __restrict__ p1,
                         const float* __restrict__ p2,
                         float* __restrict__ out)
{
    int t = blockIdx.x * blockDim.x + threadIdx.x;
    if (t >= N_ANCH) return;

    const float* p; int G, HW, off, sc; float st;
    if (t < OFF1)      { p = p0; G = 52; HW = HW0; off = 0;    sc = 0; st =  8.f; }
    else if (t < OFF2) { p = p1; G = 26; HW = HW1; off = OFF1; sc = 1; st = 16.f; }
    else               { p = p2; G = 13; HW = HW2; off = OFF2; sc = 2; st = 32.f; }

    int rel = t - off;
    int a   = rel / HW;
    int hw  = rel - a * HW;
    int y   = hw / G;
    int x   = hw - y * G;
    int GG  = HW;
    int idx = off + hw * 3 + a;                // original anchor index
    const float* base = p + hw;                // batch 0, channel stride = GG

    float obj = sigmoidf_(base[(size_t)a * GG]);

    float l[NCLS];
    float m = -3.4e38f; int am = 0;
#pragma unroll
    for (int c = 0; c < NCLS; c++) {
        l[c] = base[(size_t)(3 + a * NCLS + c) * GG];
        if (l[c] > m) { m = l[c]; am = c; }
    }
    float s = 0.f;
#pragma unroll
    for (int c = 0; c < NCLS; c++) s += expf(l[c] - m);
    float score = obj * (1.f / s);

    float tx = base[(size_t)(63 + a * 4 + 0) * GG];
    float ty = base[(size_t)(63 + a * 4 + 1) * GG];
    float tw = base[(size_t)(63 + a * 4 + 2) * GG];
    float th = base[(size_t)(63 + a * 4 + 3) * GG];

    float cx = sigmoidf_(tx) + (float)x;
    float cy = sigmoidf_(ty) + (float)y;

    float aw, ah;
    if (hw == GG - 1) { aw = 0.f; ah = 0.f; }
    else { aw = c_anch[sc][a][0]; ah = c_anch[sc][a][1]; }

    float bw = expf(tw) * aw;
    float bh = expf(th) * ah;

    float x1 = (cx - bw * 0.5f) * st / 416.f;
    float y1 = (cy - bh * 0.5f) * st / 416.f;
    float x2 = (cx + bw * 0.5f) * st / 416.f;
    float y2 = (cy + bh * 0.5f) * st / 416.f;

    d_boxes[idx] = make_float4(x1, y1, x2, y2);

    unsigned long long key =
        ((unsigned long long)(~__float_as_uint(score)) << 32) | (unsigned)idx;
    int pos = atomicAdd(&d_ccnt[am], 1);
    if (pos < CCAP) d_ckey[am * CCAP + pos] = key;

    float4 ob;
    ob.x = fminf(fmaxf(x1 * 416.f, 0.f), 415.f) / 416.f;
    ob.y = fminf(fmaxf(y1 * 416.f, 0.f), 415.f) / 416.f;
    ob.z = fminf(fmaxf(x2 * 416.f, 0.f), 415.f) / 416.f;
    ob.w = fminf(fmaxf(y2 * 416.f, 0.f), 415.f) / 416.f;
    *(float4*)(out + (size_t)idx * 4) = ob;
    out[4 * N_ANCH + idx] = score;
    out[5 * N_ANCH + idx] = (float)am;
}

// ---------------- kernel 2: hybrid register/shfl bitonic sort + gather ----------------
__global__ void __launch_bounds__(1024) k_sortgather()
{
    __shared__ unsigned long long sx[CCAP];    // exchange buffer for j>=32 steps
    const int c    = blockIdx.x;
    const int tid  = threadIdx.x;
    const int lane = tid & 31;
    const int wrp  = tid >> 5;

    int nc = d_ccnt[c];
    if (nc > CCAP) nc = CCAP;

    unsigned long long v = (tid < nc) ? d_ckey[c * CCAP + tid] : 0xFFFFFFFFFFFFFFFFULL;

    // bitonic: real keys are distinct (idx in low bits) -> min/max comparator safe
    for (int k = 2; k <= CCAP; k <<= 1) {
        int j = k >> 1;
        for (; j >= 32; j >>= 1) {             // cross-warp: smem exchange
            sx[tid] = v;
            __syncthreads();
            unsigned long long o = sx[tid ^ j];
            bool takeMin = (((tid & j) == 0) == ((tid & k) == 0));
            v = takeMin ? (v < o ? v : o) : (v < o ? o : v);
            __syncthreads();
        }
        for (; j > 0; j >>= 1) {               // intra-warp: shfl, no barriers
            unsigned long long o = __shfl_xor_sync(0xFFFFFFFFu, v, j);
            bool takeMin = (((lane & j) == 0) == ((tid & k) == 0));
            v = takeMin ? (v < o ? v : o) : (v < o ? o : v);
        }
    }

    // thread tid now holds rank-tid element
    d_skey[c * CCAP + tid] = v;
    bool valid = false;
    if (tid < nc) {
        int o = (int)(v & 0xFFFFFFFFULL);
        float4 b = d_boxes[o];
        d_sbox [c * CCAP + tid] = b;
        d_sarea[c * CCAP + tid] = (b.z - b.x) * (b.w - b.y);
        valid = (__uint_as_float(~(unsigned)(v >> 32)) >= CONF_T);
    }
    unsigned vb = __ballot_sync(0xFFFFFFFFu, valid);
    if (lane == 0) d_validw[c * 32 + wrp] = vb;
    if (tid < 32) { d_colany[c * 32 + tid] = 0u; d_rowany[c * 32 + tid] = 0u; }
    if (tid == 0) { d_snc[c] = nc; d_ccnt[c] = 0; }   // self-reset for next replay
}

// ---------------- kernel 3: conflict-mask build, 8 strips x 20 classes ----------------
__global__ void __launch_bounds__(256) k_build()
{
    __shared__ float4 sb[CCAP];
    __shared__ float  sa[CCAP];
    const int c   = blockIdx.y;
    const int s   = blockIdx.x;
    const int tid = threadIdx.x;

    const int nc = d_snc[c];
    const int nwords = (nc + 31) >> 5;
    if (s >= nwords) return;

    for (int i = tid; i < nc; i += 256) {
        sb[i] = d_sbox [c * CCAP + i];
        sa[i] = d_sarea[c * CCAP + i];
    }
    __syncthreads();

    // interleaved words for balance: w = s, s+8, s+16, ...
    for (int w = s; w < nwords; w += STRIPS) {
        int j0   = w << 5;
        int rows = min(nc, j0 + 32);           // rows >= j0+32 have structurally-zero masks
        for (int i = tid; i < rows; i += 256) { // lanes: consecutive i, shared w -> broadcast loads
            float4 bi = sb[i];
            float  ai = sa[i];
            unsigned bits = 0u;
#pragma unroll
            for (int u = 0; u < 32; u++) {
                int j = j0 + u;
                float4 bj = sb[j];             // broadcast across lanes
                float xx1 = fmaxf(bi.x, bj.x);
                float yy1 = fmaxf(bi.y, bj.y);
                float xx2 = fminf(bi.z, bj.z);
                float yy2 = fminf(bi.w, bj.w);
                float inter = fmaxf(1e-28f, xx2 - xx1) * fmaxf(1e-28f, yy2 - yy1);
                float denom = ai + sa[j] - inter;
                // iou > 0.5 exactly: denom>0 -> inter>denom/2; denom==0 -> inter>0; denom<0 -> never
                bool conf = (j > i) && (j < nc) && (denom >= 0.f) && (inter > 0.5f * denom);
                bits |= ((unsigned)conf) << u;
            }
            d_masks[((size_t)c * CCAP + i) * MAXW + w] = bits;
            if (bits) {
                atomicOr(&d_colany[c * 32 + w], bits);
                atomicOr(&d_rowany[c * 32 + (i >> 5)], 1u << (i & 31));
            }
        }
    }
}

// ---------------- kernel 4: Jacobi fixed-point NMS over involved rows ----------------
// K^{t+1} = valid & ~supp(K^t), K^0 = valid. Antitone operator: even/odd iterates
// sandwich the greedy solution; on the index-ordered DAG (masks strictly upper-
// triangular) the bounds provably meet at exactly the greedy-NMS keep set.
__global__ void __launch_bounds__(1024) k_sweep(float* __restrict__ out)
{
    extern __shared__ unsigned int smask[];    // ninv rows, pitch SPITCH (worst 132 KB)
    __shared__ int          rows_s[CCAP];      // compacted involved-row indices (ascending)
    __shared__ unsigned int validw_s[32], inv_s[32], keep_s[32], supp_s[32];
    __shared__ int          P[33];             // prefix offsets of involved rows per word
    __shared__ int          changed;

    const int c    = blockIdx.x;
    const int tid  = threadIdx.x;
    const int lane = tid & 31;
    const int w    = tid >> 5;                 // warp id == supp word this warp owns
    const int nc   = d_snc[c];
    const int nwords = (nc + 31) >> 5;

    if (tid < 32) {
        unsigned ca = d_colany[c * 32 + tid];
        unsigned ra = d_rowany[c * 32 + tid];
        unsigned va = d_validw[c * 32 + tid];
        validw_s[tid] = va;
        keep_s[tid]   = va;                    // K^0 = valid
        unsigned iv   = ca | ra;               // rows participating in any conflict
        inv_s[tid]    = iv;
        // warp-parallel inclusive scan of popcounts -> prefix table
        int scan = __popc(iv);
#pragma unroll
        for (int d = 1; d < 32; d <<= 1) {
            int nvl = __shfl_up_sync(0xFFFFFFFFu, scan, d);
            if (lane >= d) scan += nvl;
        }
        P[tid + 1] = scan;
        if (tid == 0) { P[0] = 0; changed = 1; }
    }
    __syncthreads();
    const int ninv = P[32];

    // compacted ascending list: rows_s[slot] = i
    if (tid < nc) {
        unsigned iw = inv_s[tid >> 5];
        if ((iw >> lane) & 1u)
            rows_s[P[tid >> 5] + __popc(iw & ((1u << lane) - 1u))] = tid;
    }
    __syncthreads();

    // copy involved rows' masks to pitch-33 smem (coalesced global, conflict-free smem)
    for (int t = tid; t < ninv * 32; t += 1024) {
        int s = t >> 5, ln = t & 31;
        int i = rows_s[s];
        smask[s * SPITCH + ln] = (ln >= (i >> 5) && ln < nwords)
                               ? d_masks[((size_t)c * CCAP + i) * MAXW + ln] : 0u;
    }
    __syncthreads();

    // Jacobi iteration (converges in ~chain-depth+2; cap is a safety bound)
    const int maxit = 2 * nc + 8;
    for (int it = 0; it < maxit && changed; it++) {
        // warp w: supp word w = OR of kept involved rows' mask word w
        unsigned acc = 0u;
        for (int s = lane; s < ninv; s += 32) {
            int i = rows_s[s];                              // conflict-free LDS
            unsigned kb = (keep_s[i >> 5] >> (i & 31)) & 1u;
            acc |= smask[s * SPITCH + w] & (0u - kb);       // pitch-33: conflict-free
        }
#pragma unroll
        for (int d = 16; d; d >>= 1) acc |= __shfl_xor_sync(0xFFFFFFFFu, acc, d);
        if (lane == 0) supp_s[w] = acc;
        __syncthreads();
        if (tid < 32) {                                     // warp 0: update + converge test
            if (tid == 0) changed = 0;
            unsigned nk = validw_s[tid] & ~supp_s[tid];
            unsigned diff = __ballot_sync(0xFFFFFFFFu, nk != keep_s[tid]);
            keep_s[tid] = nk;
            if (tid == 0 && diff) changed = 1;
        }
        __syncthreads();
    }

    // scatter keep flags back to original indices
    for (int r = tid; r < nc; r += 1024) {
        int o = (int)(d_skey[c * CCAP + r] & 0xFFFFFFFFULL);
        out[6 * N_ANCH + o] = ((keep_s[r >> 5] >> (r & 31)) & 1u) ? 1.f : 0.f;
    }
}

// ---------------- launch ----------------
extern "C" void kernel_launch(void* const* d_in, const int* in_sizes, int n_in,
                              void* d_out, int out_size)
{
    const float* p0 = (const float*)d_in[0];   // pred_1 (64,75,52,52)
    const float* p1 = (const float*)d_in[1];   // pred_2 (64,75,26,26)
    const float* p2 = (const float*)d_in[2];   // pred_3 (64,75,13,13)
    float* out = (float*)d_out;

    const int sweep_smem = CCAP * SPITCH * 4;  // worst-case 132 KB (all rows involved)
    cudaFuncSetAttribute(k_sweep, cudaFuncAttributeMaxDynamicSharedMemorySize, sweep_smem);

    k_decode    <<<(N_ANCH + 127) / 128, 128>>>(p0, p1, p2, out);
    k_sortgather<<<NCLS, 1024>>>();
    k_build     <<<dim3(STRIPS, NCLS), 256>>>();
    k_sweep     <<<NCLS, 1024, sweep_smem>>>(out);
}